// round 6
// baseline (speedup 1.0000x reference)
#include <cuda_runtime.h>
#include <cuda_fp16.h>
#include <cstdint>

// Problem dims (fixed by the reference)
#define NB   8
#define NL   256
#define ND1  512
#define ND2  512
#define NK   64
#define NBI  (NB * NL)   // 2048

// ---------------------------------------------------------------------------
// Scratch (static __device__ arrays: allocation-guard-safe)
// ---------------------------------------------------------------------------
__device__ __half g_x1h[NBI * ND1];                       // x1 fp16              (2 MB)
__device__ __half g_x2h[NBI * ND2];                       // x2 fp16              (2 MB)
__device__ __half g_wt [(size_t)NK * ND2 * ND1];          // W^T [k][q][p] fp16   (32 MB)
__device__ __half g_tmp[(size_t)NBI * NK * ND2];          // tmp [bi][k][q] fp16  (128 MB)

// ---------------------------------------------------------------------------
// Portable (sm_80-level) PTX helpers — NO 'a'-gated features anywhere
// ---------------------------------------------------------------------------
__device__ __forceinline__ uint32_t smem_u32(const void* p) {
    uint32_t a;
    asm("{ .reg .u64 t; cvta.to.shared.u64 t, %1; cvt.u32.u64 %0, t; }" : "=r"(a) : "l"(p));
    return a;
}

__device__ __forceinline__ void cp16(uint32_t saddr, const void* gaddr) {
    asm volatile("cp.async.cg.shared.global [%0], [%1], 16;" :: "r"(saddr), "l"(gaddr));
}
__device__ __forceinline__ void cp_commit() {
    asm volatile("cp.async.commit_group;" ::: "memory");
}
template <int N>
__device__ __forceinline__ void cp_wait() {
    asm volatile("cp.async.wait_group %0;" :: "n"(N) : "memory");
}

__device__ __forceinline__ void ldm4(uint32_t& r0, uint32_t& r1, uint32_t& r2, uint32_t& r3,
                                     uint32_t addr) {
    asm volatile("ldmatrix.sync.aligned.m8n8.x4.shared.b16 {%0,%1,%2,%3}, [%4];"
                 : "=r"(r0), "=r"(r1), "=r"(r2), "=r"(r3) : "r"(addr));
}

__device__ __forceinline__ void mma16816(float* d, const uint32_t* a, const uint32_t* b) {
    asm volatile(
        "mma.sync.aligned.m16n8k16.row.col.f32.f16.f16.f32 "
        "{%0,%1,%2,%3}, {%4,%5,%6,%7}, {%8,%9}, {%0,%1,%2,%3};"
        : "+f"(d[0]), "+f"(d[1]), "+f"(d[2]), "+f"(d[3])
        : "r"(a[0]), "r"(a[1]), "r"(a[2]), "r"(a[3]), "r"(b[0]), "r"(b[1]));
}

__device__ __forceinline__ uint32_t f22h2(float lo, float hi) {
    uint32_t r;
    asm("cvt.rn.f16x2.f32 %0, %1, %2;" : "=r"(r) : "f"(hi), "f"(lo));
    return r;
}

// ---------------------------------------------------------------------------
// Kernel 1: convert x1/x2 fp32 -> fp16 (vectorized, both in one launch)
// ---------------------------------------------------------------------------
__global__ void __launch_bounds__(256) convert_inputs_kernel(const float* __restrict__ x1,
                                                             const float* __restrict__ x2) {
    const int idx = blockIdx.x * blockDim.x + threadIdx.x;  // 0 .. NBI*ND1/4-1
    float4 v1 = __ldg((const float4*)x1 + idx);
    float4 v2 = __ldg((const float4*)x2 + idx);
    uint2 o1, o2;
    o1.x = f22h2(v1.x, v1.y); o1.y = f22h2(v1.z, v1.w);
    o2.x = f22h2(v2.x, v2.y); o2.y = f22h2(v2.z, v2.w);
    ((uint2*)g_x1h)[idx] = o1;
    ((uint2*)g_x2h)[idx] = o2;
}

// ---------------------------------------------------------------------------
// Kernel 2: W [k][p][q] fp32 -> Wt [k][q][p] fp16 (32x32 smem transpose)
// ---------------------------------------------------------------------------
__global__ void __launch_bounds__(256) transpose_w_kernel(const float* __restrict__ W) {
    __shared__ float tile[32][33];
    const int k  = blockIdx.z;
    const int p0 = blockIdx.x * 32;
    const int q0 = blockIdx.y * 32;
    const float* Wk = W + (size_t)k * ND1 * ND2;
#pragma unroll
    for (int yy = 0; yy < 32; yy += 8)
        tile[threadIdx.y + yy][threadIdx.x] =
            __ldg(&Wk[(size_t)(p0 + threadIdx.y + yy) * ND2 + q0 + threadIdx.x]);
    __syncthreads();
    __half* Wtk = g_wt + (size_t)k * ND2 * ND1;
#pragma unroll
    for (int yy = 0; yy < 32; yy += 8)
        Wtk[(size_t)(q0 + threadIdx.y + yy) * ND1 + p0 + threadIdx.x] =
            __float2half_rn(tile[threadIdx.x][threadIdx.y + yy]);
}

// ---------------------------------------------------------------------------
// GEMM1: tmp[bi][k][q] = sum_p x1h[bi][p] * Wt[k][q][p]   (TN, both K-major)
//   grid = (16 m-tiles of 128 bi, 4 q-tiles of 128, 64 k)
//   CTA tile 128x128, kc=64 halves, cp.async double buffered, 8 warps (4x2)
//   warp tile 32x64: per k16 step = 2 ldm4(A) + 4 ldm4(B) + 16 mma
// ---------------------------------------------------------------------------
#define G1_LDA   144u                    // 64 halves (128B) + 16B pad per row
#define G1_ASZ   (128u * G1_LDA)         // 18432
#define G1_BSZ   (128u * G1_LDA)         // 18432
#define G1_STAGE (G1_ASZ + G1_BSZ)       // 36864
#define G1_SMEM  (2u * G1_STAGE)         // 73728

__global__ void __launch_bounds__(256) gemm1_kernel() {
    extern __shared__ char smem[];
    const int tid  = threadIdx.x;
    const int lane = tid & 31;
    const int wid  = tid >> 5;
    const int m0   = blockIdx.x * 128;
    const int q0   = blockIdx.y * 128;
    const int kb   = blockIdx.z;
    const uint32_t sb = smem_u32(smem);

    const __half* Ag = g_x1h + (size_t)m0 * ND1;
    const __half* Bg = g_wt + ((size_t)kb * ND2 + q0) * ND1;

    auto load_chunk = [&](int c, int buf) {
        uint32_t sA = sb + (uint32_t)buf * G1_STAGE;
        uint32_t sB = sA + G1_ASZ;
#pragma unroll
        for (int it = 0; it < 4; ++it) {
            int idx = tid + it * 256;
            int r = idx >> 3, col = idx & 7;
            cp16(sA + (uint32_t)r * G1_LDA + col * 16, Ag + (size_t)r * ND1 + c * 64 + col * 8);
        }
#pragma unroll
        for (int it = 0; it < 4; ++it) {
            int idx = tid + it * 256;
            int r = idx >> 3, col = idx & 7;
            cp16(sB + (uint32_t)r * G1_LDA + col * 16, Bg + (size_t)r * ND1 + c * 64 + col * 8);
        }
        cp_commit();
    };

    float d[2][8][4];
#pragma unroll
    for (int mi = 0; mi < 2; ++mi)
#pragma unroll
        for (int ni = 0; ni < 8; ++ni)
#pragma unroll
            for (int e = 0; e < 4; ++e) d[mi][ni][e] = 0.0f;

    const int m_base = (wid >> 1) * 32;
    const int n_base = (wid & 1) * 64;
    // ldmatrix lane address offsets (bytes)
    const uint32_t a_lane = (uint32_t)(m_base + (lane & 15)) * G1_LDA + ((lane & 16) ? 16u : 0u);
    const uint32_t b_lane = (uint32_t)(n_base + (lane & 7) + ((lane & 16) ? 8 : 0)) * G1_LDA +
                            ((lane & 8) ? 16u : 0u);

    load_chunk(0, 0);
#pragma unroll 1
    for (int c = 0; c < 8; ++c) {
        const int buf = c & 1;
        if (c + 1 < 8) load_chunk(c + 1, buf ^ 1);
        if (c + 1 < 8) cp_wait<1>(); else cp_wait<0>();
        __syncthreads();
        const uint32_t sA = sb + (uint32_t)buf * G1_STAGE;
        const uint32_t sB = sA + G1_ASZ;
#pragma unroll
        for (int s = 0; s < 4; ++s) {
            uint32_t a[2][4];
            ldm4(a[0][0], a[0][1], a[0][2], a[0][3], sA + a_lane + s * 32);
            ldm4(a[1][0], a[1][1], a[1][2], a[1][3], sA + a_lane + 16 * G1_LDA + s * 32);
            uint32_t b[8][2];
#pragma unroll
            for (int nj = 0; nj < 4; ++nj) {
                uint32_t r0, r1, r2, r3;
                ldm4(r0, r1, r2, r3, sB + b_lane + nj * 16 * G1_LDA + s * 32);
                b[2 * nj][0] = r0; b[2 * nj][1] = r1;
                b[2 * nj + 1][0] = r2; b[2 * nj + 1][1] = r3;
            }
#pragma unroll
            for (int mi = 0; mi < 2; ++mi)
#pragma unroll
                for (int ni = 0; ni < 8; ++ni)
                    mma16816(d[mi][ni], a[mi], b[ni]);
        }
        __syncthreads();
    }

    // Epilogue: fp32 accum -> fp16 tmp[bi][k][q] (half2 stores, 16B per quad)
    {
        const int r_lane = lane >> 2;
        const int c_lane = (lane & 3) << 1;
#pragma unroll
        for (int mi = 0; mi < 2; ++mi) {
            const int row = m0 + m_base + mi * 16 + r_lane;
            __half* base = g_tmp + ((size_t)row * NK + kb) * ND2 + q0 + n_base + c_lane;
#pragma unroll
            for (int ni = 0; ni < 8; ++ni) {
                *(__half2*)(base + ni * 8) = __floats2half2_rn(d[mi][ni][0], d[mi][ni][1]);
                *(__half2*)(base + ni * 8 + (size_t)8 * NK * ND2) =
                    __floats2half2_rn(d[mi][ni][2], d[mi][ni][3]);
            }
        }
    }
}

// ---------------------------------------------------------------------------
// GEMM2: out[bi][j][k] = sum_q x2h[b][j][q] * tmp[bi][k][q] + bias[k]
//   grid = (2 j-tiles of 128, 2048 bi). CTA tile 128x64, kc=64, 8 warps (4x2)
//   warp tile 32x32: per k16 step = 2 ldm4(A) + 2 ldm4(B) + 8 mma
// ---------------------------------------------------------------------------
#define G2_LDA   144u
#define G2_ASZ   (128u * G2_LDA)         // 18432
#define G2_BSZ   (64u * G2_LDA)          // 9216
#define G2_STAGE (G2_ASZ + G2_BSZ)       // 27648
#define G2_SMEM  (2u * G2_STAGE)         // 55296

__global__ void __launch_bounds__(256) gemm2_kernel(const float* __restrict__ bias,
                                                    float* __restrict__ out) {
    __shared__ float sbias[64];
    extern __shared__ char smem[];
    const int tid  = threadIdx.x;
    const int lane = tid & 31;
    const int wid  = tid >> 5;
    const int j0   = blockIdx.x * 128;
    const int bi   = blockIdx.y;
    const int b    = bi >> 8;
    const uint32_t sb = smem_u32(smem);

    if (tid < 64) sbias[tid] = __ldg(bias + tid);

    const __half* Ag = g_x2h + ((size_t)(b * NL) + j0) * ND2;
    const __half* Bg = g_tmp + (size_t)bi * NK * ND2;

    auto load_chunk = [&](int c, int buf) {
        uint32_t sA = sb + (uint32_t)buf * G2_STAGE;
        uint32_t sB = sA + G2_ASZ;
#pragma unroll
        for (int it = 0; it < 4; ++it) {
            int idx = tid + it * 256;
            int r = idx >> 3, col = idx & 7;
            cp16(sA + (uint32_t)r * G2_LDA + col * 16, Ag + (size_t)r * ND2 + c * 64 + col * 8);
        }
#pragma unroll
        for (int it = 0; it < 2; ++it) {
            int idx = tid + it * 256;
            int r = idx >> 3, col = idx & 7;
            cp16(sB + (uint32_t)r * G2_LDA + col * 16, Bg + (size_t)r * ND2 + c * 64 + col * 8);
        }
        cp_commit();
    };

    float d[2][4][4];
#pragma unroll
    for (int mi = 0; mi < 2; ++mi)
#pragma unroll
        for (int ni = 0; ni < 4; ++ni)
#pragma unroll
            for (int e = 0; e < 4; ++e) d[mi][ni][e] = 0.0f;

    const int m_base = (wid >> 1) * 32;
    const int n_base = (wid & 1) * 32;
    const uint32_t a_lane = (uint32_t)(m_base + (lane & 15)) * G2_LDA + ((lane & 16) ? 16u : 0u);
    const uint32_t b_lane = (uint32_t)(n_base + (lane & 7) + ((lane & 16) ? 8 : 0)) * G2_LDA +
                            ((lane & 8) ? 16u : 0u);

    load_chunk(0, 0);
#pragma unroll 1
    for (int c = 0; c < 8; ++c) {
        const int buf = c & 1;
        if (c + 1 < 8) load_chunk(c + 1, buf ^ 1);
        if (c + 1 < 8) cp_wait<1>(); else cp_wait<0>();
        __syncthreads();
        const uint32_t sA = sb + (uint32_t)buf * G2_STAGE;
        const uint32_t sB = sA + G2_ASZ;
#pragma unroll
        for (int s = 0; s < 4; ++s) {
            uint32_t a[2][4];
            ldm4(a[0][0], a[0][1], a[0][2], a[0][3], sA + a_lane + s * 32);
            ldm4(a[1][0], a[1][1], a[1][2], a[1][3], sA + a_lane + 16 * G2_LDA + s * 32);
            uint32_t bfr[4][2];
#pragma unroll
            for (int nj = 0; nj < 2; ++nj) {
                uint32_t r0, r1, r2, r3;
                ldm4(r0, r1, r2, r3, sB + b_lane + nj * 16 * G2_LDA + s * 32);
                bfr[2 * nj][0] = r0; bfr[2 * nj][1] = r1;
                bfr[2 * nj + 1][0] = r2; bfr[2 * nj + 1][1] = r3;
            }
#pragma unroll
            for (int mi = 0; mi < 2; ++mi)
#pragma unroll
                for (int ni = 0; ni < 4; ++ni)
                    mma16816(d[mi][ni], a[mi], bfr[ni]);
        }
        __syncthreads();
    }

    // Epilogue: + bias -> out[bi][j][k] (float2 stores)
    {
        const int r_lane = lane >> 2;
        const int c_lane = (lane & 3) << 1;
#pragma unroll
        for (int mi = 0; mi < 2; ++mi) {
            const int jrow = j0 + m_base + mi * 16 + r_lane;
            float* base = out + ((size_t)bi * NL + jrow) * NK;
#pragma unroll
            for (int ni = 0; ni < 4; ++ni) {
                const int kc0 = n_base + ni * 8 + c_lane;
                const float b0 = sbias[kc0], b1 = sbias[kc0 + 1];
                *(float2*)(base + kc0) = make_float2(d[mi][ni][0] + b0, d[mi][ni][1] + b1);
                *(float2*)(base + 8 * NK + kc0) = make_float2(d[mi][ni][2] + b0, d[mi][ni][3] + b1);
            }
        }
    }
}

// ---------------------------------------------------------------------------
// Launch
// ---------------------------------------------------------------------------
extern "C" void kernel_launch(void* const* d_in, const int* in_sizes, int n_in,
                              void* d_out, int out_size) {
    const float* x1   = (const float*)d_in[0];
    const float* x2   = (const float*)d_in[1];
    const float* W    = (const float*)d_in[2];
    const float* bias = (const float*)d_in[3];
    float* out = (float*)d_out;

    cudaFuncSetAttribute(gemm1_kernel, cudaFuncAttributeMaxDynamicSharedMemorySize, G1_SMEM);
    cudaFuncSetAttribute(gemm2_kernel, cudaFuncAttributeMaxDynamicSharedMemorySize, G2_SMEM);

    convert_inputs_kernel<<<1024, 256>>>(x1, x2);
    transpose_w_kernel<<<dim3(16, 16, 64), dim3(32, 8)>>>(W);
    gemm1_kernel<<<dim3(16, 4, 64), 256, G1_SMEM>>>();
    gemm2_kernel<<<dim3(2, 2048), 256, G2_SMEM>>>(bias, out);
}

// round 8
// speedup vs baseline: 1.8448x; 1.8448x over previous
#include <cuda_runtime.h>
#include <cuda_fp16.h>
#include <cstdint>

// Problem dims (fixed by the reference)
#define NB   8
#define NL   256
#define ND1  512
#define ND2  512
#define NK   64
#define NBI  (NB * NL)   // 2048

// ---------------------------------------------------------------------------
// Scratch (static __device__ arrays: allocation-guard-safe)
// ---------------------------------------------------------------------------
__device__ __half g_x1h[NBI * ND1];                       // x1 fp16              (2 MB)
__device__ __half g_x2h[NBI * ND2];                       // x2 fp16              (2 MB)
__device__ __half g_wt [(size_t)NK * ND2 * ND1];          // W^T [k][q][p] fp16   (32 MB)
__device__ __half g_tmp[(size_t)NBI * NK * ND2];          // tmp [bi][k][q] fp16  (128 MB)

// ---------------------------------------------------------------------------
// Portable (sm_80-level) PTX helpers — NO 'a'-gated features anywhere
// ---------------------------------------------------------------------------
__device__ __forceinline__ uint32_t smem_u32(const void* p) {
    uint32_t a;
    asm("{ .reg .u64 t; cvta.to.shared.u64 t, %1; cvt.u32.u64 %0, t; }" : "=r"(a) : "l"(p));
    return a;
}

__device__ __forceinline__ void cp16(uint32_t saddr, const void* gaddr) {
    asm volatile("cp.async.cg.shared.global [%0], [%1], 16;" :: "r"(saddr), "l"(gaddr));
}
__device__ __forceinline__ void cp_commit() {
    asm volatile("cp.async.commit_group;" ::: "memory");
}
template <int N>
__device__ __forceinline__ void cp_wait() {
    asm volatile("cp.async.wait_group %0;" :: "n"(N) : "memory");
}

__device__ __forceinline__ void ldm4(uint32_t& r0, uint32_t& r1, uint32_t& r2, uint32_t& r3,
                                     uint32_t addr) {
    asm volatile("ldmatrix.sync.aligned.m8n8.x4.shared.b16 {%0,%1,%2,%3}, [%4];"
                 : "=r"(r0), "=r"(r1), "=r"(r2), "=r"(r3) : "r"(addr));
}

__device__ __forceinline__ void mma16816(float* d, const uint32_t* a, const uint32_t* b) {
    asm volatile(
        "mma.sync.aligned.m16n8k16.row.col.f32.f16.f16.f32 "
        "{%0,%1,%2,%3}, {%4,%5,%6,%7}, {%8,%9}, {%0,%1,%2,%3};"
        : "+f"(d[0]), "+f"(d[1]), "+f"(d[2]), "+f"(d[3])
        : "r"(a[0]), "r"(a[1]), "r"(a[2]), "r"(a[3]), "r"(b[0]), "r"(b[1]));
}

__device__ __forceinline__ uint32_t f22h2(float lo, float hi) {
    uint32_t r;
    asm("cvt.rn.f16x2.f32 %0, %1, %2;" : "=r"(r) : "f"(hi), "f"(lo));
    return r;
}

// XOR swizzle: tile rows are 128B (8 x 16B chunks); chunk column c of row r
// lives at (c ^ (r & 7)) * 16. Conflict-free for both cp.async stores and
// ldmatrix reads; needs no row padding (saves smem vs +16B pad).
__device__ __forceinline__ uint32_t swz(uint32_t r, uint32_t c) {
    return r * 128u + ((c ^ (r & 7u)) << 4);
}

// ---------------------------------------------------------------------------
// Kernel 1: convert x1/x2 fp32 -> fp16 (vectorized, both in one launch)
// ---------------------------------------------------------------------------
__global__ void __launch_bounds__(256) convert_inputs_kernel(const float* __restrict__ x1,
                                                             const float* __restrict__ x2) {
    const int idx = blockIdx.x * blockDim.x + threadIdx.x;
    float4 v1 = __ldg((const float4*)x1 + idx);
    float4 v2 = __ldg((const float4*)x2 + idx);
    uint2 o1, o2;
    o1.x = f22h2(v1.x, v1.y); o1.y = f22h2(v1.z, v1.w);
    o2.x = f22h2(v2.x, v2.y); o2.y = f22h2(v2.z, v2.w);
    ((uint2*)g_x1h)[idx] = o1;
    ((uint2*)g_x2h)[idx] = o2;
}

// ---------------------------------------------------------------------------
// Kernel 2: W [k][p][q] fp32 -> Wt [k][q][p] fp16 (32x32 smem transpose)
// ---------------------------------------------------------------------------
__global__ void __launch_bounds__(256) transpose_w_kernel(const float* __restrict__ W) {
    __shared__ float tile[32][33];
    const int k  = blockIdx.z;
    const int p0 = blockIdx.x * 32;
    const int q0 = blockIdx.y * 32;
    const float* Wk = W + (size_t)k * ND1 * ND2;
#pragma unroll
    for (int yy = 0; yy < 32; yy += 8)
        tile[threadIdx.y + yy][threadIdx.x] =
            __ldg(&Wk[(size_t)(p0 + threadIdx.y + yy) * ND2 + q0 + threadIdx.x]);
    __syncthreads();
    __half* Wtk = g_wt + (size_t)k * ND2 * ND1;
#pragma unroll
    for (int yy = 0; yy < 32; yy += 8)
        Wtk[(size_t)(q0 + threadIdx.y + yy) * ND1 + p0 + threadIdx.x] =
            __float2half_rn(tile[threadIdx.x][threadIdx.y + yy]);
}

// ---------------------------------------------------------------------------
// GEMM1: tmp[bi][k][q] = sum_p x1h[bi][p] * Wt[k][q][p]   (TN, both K-major)
//   grid = (16 m-tiles of 128 bi, 4 q-tiles of 128, 64 k)
//   CTA 128x128, kc=64, 3-stage cp.async, 8 warps (2m x 4n), warp tile 64x32
//   per k16 step: 4 ldm4(A) + 2 ldm4(B) -> 16 mma
// ---------------------------------------------------------------------------
#define G1_ASZ   (128u * 128u)           // 16384
#define G1_BSZ   (128u * 128u)           // 16384
#define G1_STAGE (G1_ASZ + G1_BSZ)       // 32768
#define G1_SMEM  (3u * G1_STAGE)         // 98304

__global__ void __launch_bounds__(256, 2) gemm1_kernel() {
    extern __shared__ char smem[];
    const int tid  = threadIdx.x;
    const int lane = tid & 31;
    const int wid  = tid >> 5;
    const int m0   = blockIdx.x * 128;
    const int q0   = blockIdx.y * 128;
    const int kb   = blockIdx.z;
    const uint32_t sb = smem_u32(smem);

    const __half* Ag = g_x1h + (size_t)m0 * ND1;
    const __half* Bg = g_wt + ((size_t)kb * ND2 + q0) * ND1;

    auto load_chunk = [&](int c, int stg) {
        uint32_t sA = sb + (uint32_t)stg * G1_STAGE;
        uint32_t sB = sA + G1_ASZ;
#pragma unroll
        for (int it = 0; it < 4; ++it) {
            int idx = tid + it * 256;
            uint32_t r = (uint32_t)(idx >> 3), col = (uint32_t)(idx & 7);
            cp16(sA + swz(r, col), Ag + (size_t)r * ND1 + c * 64 + col * 8);
        }
#pragma unroll
        for (int it = 0; it < 4; ++it) {
            int idx = tid + it * 256;
            uint32_t r = (uint32_t)(idx >> 3), col = (uint32_t)(idx & 7);
            cp16(sB + swz(r, col), Bg + (size_t)r * ND1 + c * 64 + col * 8);
        }
        cp_commit();
    };

    float d[4][4][4];
#pragma unroll
    for (int mf = 0; mf < 4; ++mf)
#pragma unroll
        for (int nf = 0; nf < 4; ++nf)
#pragma unroll
            for (int e = 0; e < 4; ++e) d[mf][nf][e] = 0.0f;

    const int m_base = (wid & 1) * 64;
    const int n_base = (wid >> 1) * 32;
    // ldmatrix lane rows / column-chunk bases (row&7 invariant under +16-row steps)
    const uint32_t a_row = (uint32_t)(m_base + (lane & 15));
    const uint32_t a_cb  = (uint32_t)((lane >> 4) & 1);
    const uint32_t a_r7  = a_row & 7u;
    const uint32_t b_row = (uint32_t)(n_base + (lane & 7) + ((lane & 16) ? 8 : 0));
    const uint32_t b_cb  = (uint32_t)((lane >> 3) & 1);
    const uint32_t b_r7  = b_row & 7u;

    load_chunk(0, 0);
    load_chunk(1, 1);
#pragma unroll 1
    for (int c = 0; c < 8; ++c) {
        if (c < 7) cp_wait<1>(); else cp_wait<0>();
        __syncthreads();
        if (c + 2 < 8) load_chunk(c + 2, (c + 2) % 3);
        const uint32_t sA = sb + (uint32_t)(c % 3) * G1_STAGE;
        const uint32_t sB = sA + G1_ASZ;
#pragma unroll
        for (int s = 0; s < 4; ++s) {
            const uint32_t swA = ((2u * s + a_cb) ^ a_r7) << 4;
            const uint32_t swB = ((2u * s + b_cb) ^ b_r7) << 4;
            uint32_t a[4][4];
#pragma unroll
            for (int mf = 0; mf < 4; ++mf)
                ldm4(a[mf][0], a[mf][1], a[mf][2], a[mf][3],
                     sA + (a_row + mf * 16) * 128u + swA);
            uint32_t b[4][2];
#pragma unroll
            for (int nj = 0; nj < 2; ++nj) {
                uint32_t r0, r1, r2, r3;
                ldm4(r0, r1, r2, r3, sB + (b_row + nj * 16) * 128u + swB);
                b[2 * nj][0] = r0; b[2 * nj][1] = r1;
                b[2 * nj + 1][0] = r2; b[2 * nj + 1][1] = r3;
            }
#pragma unroll
            for (int mf = 0; mf < 4; ++mf)
#pragma unroll
                for (int nf = 0; nf < 4; ++nf)
                    mma16816(d[mf][nf], a[mf], b[nf]);
        }
    }

    // Epilogue: fp32 accum -> fp16 tmp[bi][k][q]
    {
        const int r_lane = lane >> 2;
        const int c_lane = (lane & 3) << 1;
#pragma unroll
        for (int mf = 0; mf < 4; ++mf) {
            const int row = m0 + m_base + mf * 16 + r_lane;
            __half* base = g_tmp + ((size_t)row * NK + kb) * ND2 + q0 + n_base + c_lane;
#pragma unroll
            for (int nf = 0; nf < 4; ++nf) {
                *(__half2*)(base + nf * 8) = __floats2half2_rn(d[mf][nf][0], d[mf][nf][1]);
                *(__half2*)(base + nf * 8 + (size_t)8 * NK * ND2) =
                    __floats2half2_rn(d[mf][nf][2], d[mf][nf][3]);
            }
        }
    }
}

// ---------------------------------------------------------------------------
// GEMM2: out[bi][j][k] = sum_q x2h[b][j][q] * tmp[bi][k][q] + bias[k]
//   grid = (2 j-tiles of 128, 2048 bi). CTA 128x64, kc=64, 3-stage,
//   4 warps (2m x 2n), warp tile 64x32. 3 CTAs/SM (73.7KB smem each).
// ---------------------------------------------------------------------------
#define G2_ASZ   (128u * 128u)           // 16384
#define G2_BSZ   (64u * 128u)            // 8192
#define G2_STAGE (G2_ASZ + G2_BSZ)       // 24576
#define G2_SMEM  (3u * G2_STAGE)         // 73728

__global__ void __launch_bounds__(128) gemm2_kernel(const float* __restrict__ bias,
                                                    float* __restrict__ out) {
    __shared__ float sbias[64];
    extern __shared__ char smem[];
    const int tid  = threadIdx.x;
    const int lane = tid & 31;
    const int wid  = tid >> 5;
    const int j0   = blockIdx.x * 128;
    const int bi   = blockIdx.y;
    const int b    = bi >> 8;
    const uint32_t sb = smem_u32(smem);

    if (tid < 64) sbias[tid] = __ldg(bias + tid);

    const __half* Ag = g_x2h + ((size_t)(b * NL) + j0) * ND2;
    const __half* Bg = g_tmp + (size_t)bi * NK * ND2;

    auto load_chunk = [&](int c, int stg) {
        uint32_t sA = sb + (uint32_t)stg * G2_STAGE;
        uint32_t sB = sA + G2_ASZ;
#pragma unroll
        for (int it = 0; it < 8; ++it) {
            int idx = tid + it * 128;
            uint32_t r = (uint32_t)(idx >> 3), col = (uint32_t)(idx & 7);
            cp16(sA + swz(r, col), Ag + (size_t)r * ND2 + c * 64 + col * 8);
        }
#pragma unroll
        for (int it = 0; it < 4; ++it) {
            int idx = tid + it * 128;
            uint32_t r = (uint32_t)(idx >> 3), col = (uint32_t)(idx & 7);
            cp16(sB + swz(r, col), Bg + (size_t)r * ND2 + c * 64 + col * 8);
        }
        cp_commit();
    };

    float d[4][4][4];
#pragma unroll
    for (int mf = 0; mf < 4; ++mf)
#pragma unroll
        for (int nf = 0; nf < 4; ++nf)
#pragma unroll
            for (int e = 0; e < 4; ++e) d[mf][nf][e] = 0.0f;

    const int m_base = (wid & 1) * 64;
    const int n_base = (wid >> 1) * 32;
    const uint32_t a_row = (uint32_t)(m_base + (lane & 15));
    const uint32_t a_cb  = (uint32_t)((lane >> 4) & 1);
    const uint32_t a_r7  = a_row & 7u;
    const uint32_t b_row = (uint32_t)(n_base + (lane & 7) + ((lane & 16) ? 8 : 0));
    const uint32_t b_cb  = (uint32_t)((lane >> 3) & 1);
    const uint32_t b_r7  = b_row & 7u;

    load_chunk(0, 0);
    load_chunk(1, 1);
#pragma unroll 1
    for (int c = 0; c < 8; ++c) {
        if (c < 7) cp_wait<1>(); else cp_wait<0>();
        __syncthreads();
        if (c + 2 < 8) load_chunk(c + 2, (c + 2) % 3);
        const uint32_t sA = sb + (uint32_t)(c % 3) * G2_STAGE;
        const uint32_t sB = sA + G2_ASZ;
#pragma unroll
        for (int s = 0; s < 4; ++s) {
            const uint32_t swA = ((2u * s + a_cb) ^ a_r7) << 4;
            const uint32_t swB = ((2u * s + b_cb) ^ b_r7) << 4;
            uint32_t a[4][4];
#pragma unroll
            for (int mf = 0; mf < 4; ++mf)
                ldm4(a[mf][0], a[mf][1], a[mf][2], a[mf][3],
                     sA + (a_row + mf * 16) * 128u + swA);
            uint32_t bfr[4][2];
#pragma unroll
            for (int nj = 0; nj < 2; ++nj) {
                uint32_t r0, r1, r2, r3;
                ldm4(r0, r1, r2, r3, sB + (b_row + nj * 16) * 128u + swB);
                bfr[2 * nj][0] = r0; bfr[2 * nj][1] = r1;
                bfr[2 * nj + 1][0] = r2; bfr[2 * nj + 1][1] = r3;
            }
#pragma unroll
            for (int mf = 0; mf < 4; ++mf)
#pragma unroll
                for (int nf = 0; nf < 4; ++nf)
                    mma16816(d[mf][nf], a[mf], bfr[nf]);
        }
    }

    // Epilogue: + bias -> out[bi][j][k] (float2 stores)
    {
        const int r_lane = lane >> 2;
        const int c_lane = (lane & 3) << 1;
#pragma unroll
        for (int mf = 0; mf < 4; ++mf) {
            const int jrow = j0 + m_base + mf * 16 + r_lane;
            float* base = out + ((size_t)bi * NL + jrow) * NK;
#pragma unroll
            for (int nf = 0; nf < 4; ++nf) {
                const int kc0 = n_base + nf * 8 + c_lane;
                const float b0 = sbias[kc0], b1 = sbias[kc0 + 1];
                *(float2*)(base + kc0) = make_float2(d[mf][nf][0] + b0, d[mf][nf][1] + b1);
                *(float2*)(base + 8 * NK + kc0) =
                    make_float2(d[mf][nf][2] + b0, d[mf][nf][3] + b1);
            }
        }
    }
}

// ---------------------------------------------------------------------------
// Launch
// ---------------------------------------------------------------------------
extern "C" void kernel_launch(void* const* d_in, const int* in_sizes, int n_in,
                              void* d_out, int out_size) {
    const float* x1   = (const float*)d_in[0];
    const float* x2   = (const float*)d_in[1];
    const float* W    = (const float*)d_in[2];
    const float* bias = (const float*)d_in[3];
    float* out = (float*)d_out;

    cudaFuncSetAttribute(gemm1_kernel, cudaFuncAttributeMaxDynamicSharedMemorySize, G1_SMEM);
    cudaFuncSetAttribute(gemm2_kernel, cudaFuncAttributeMaxDynamicSharedMemorySize, G2_SMEM);

    convert_inputs_kernel<<<1024, 256>>>(x1, x2);
    transpose_w_kernel<<<dim3(16, 16, 64), dim3(32, 8)>>>(W);
    gemm1_kernel<<<dim3(16, 4, 64), 256, G1_SMEM>>>();
    gemm2_kernel<<<dim3(2, 2048), 128, G2_SMEM>>>(bias, out);
}

// round 10
// speedup vs baseline: 1.8464x; 1.0009x over previous
#include <cuda_runtime.h>
#include <cuda_fp16.h>
#include <cstdint>

// Problem dims (fixed by the reference)
#define NB   8
#define NL   256
#define ND1  512
#define ND2  512
#define NK   64
#define NBI  (NB * NL)   // 2048

// ---------------------------------------------------------------------------
// Scratch (static __device__ arrays: allocation-guard-safe)
// ---------------------------------------------------------------------------
__device__ __half g_x1h[NBI * ND1];                       // x1 fp16              (2 MB)
__device__ __half g_x2h[NBI * ND2];                       // x2 fp16              (2 MB)
__device__ __half g_wt [(size_t)NK * ND2 * ND1];          // W^T [k][q][p] fp16   (32 MB)
__device__ __half g_tmp[(size_t)NBI * NK * ND2];          // tmp [bi][k][q] fp16  (128 MB)

// ---------------------------------------------------------------------------
// Portable (sm_80-level) PTX helpers — NO 'a'-gated features anywhere
// ---------------------------------------------------------------------------
__device__ __forceinline__ uint32_t smem_u32(const void* p) {
    uint32_t a;
    asm("{ .reg .u64 t; cvta.to.shared.u64 t, %1; cvt.u32.u64 %0, t; }" : "=r"(a) : "l"(p));
    return a;
}

__device__ __forceinline__ void cp16(uint32_t saddr, const void* gaddr) {
    asm volatile("cp.async.cg.shared.global [%0], [%1], 16;" :: "r"(saddr), "l"(gaddr));
}
__device__ __forceinline__ void cp_commit() {
    asm volatile("cp.async.commit_group;" ::: "memory");
}
template <int N>
__device__ __forceinline__ void cp_wait() {
    asm volatile("cp.async.wait_group %0;" :: "n"(N) : "memory");
}

__device__ __forceinline__ void ldm4(uint32_t& r0, uint32_t& r1, uint32_t& r2, uint32_t& r3,
                                     uint32_t addr) {
    asm volatile("ldmatrix.sync.aligned.m8n8.x4.shared.b16 {%0,%1,%2,%3}, [%4];"
                 : "=r"(r0), "=r"(r1), "=r"(r2), "=r"(r3) : "r"(addr));
}

__device__ __forceinline__ void mma16816(float* d, const uint32_t* a, const uint32_t* b) {
    asm volatile(
        "mma.sync.aligned.m16n8k16.row.col.f32.f16.f16.f32 "
        "{%0,%1,%2,%3}, {%4,%5,%6,%7}, {%8,%9}, {%0,%1,%2,%3};"
        : "+f"(d[0]), "+f"(d[1]), "+f"(d[2]), "+f"(d[3])
        : "r"(a[0]), "r"(a[1]), "r"(a[2]), "r"(a[3]), "r"(b[0]), "r"(b[1]));
}

__device__ __forceinline__ uint32_t f22h2(float lo, float hi) {
    uint32_t r;
    asm("cvt.rn.f16x2.f32 %0, %1, %2;" : "=r"(r) : "f"(hi), "f"(lo));
    return r;
}

// XOR swizzle: tile rows are 128B (8 x 16B chunks); chunk column c of row r
// lives at (c ^ (r & 7)) * 16. Conflict-free for cp.async stores and
// ldmatrix reads; no row padding needed.
__device__ __forceinline__ uint32_t swz(uint32_t r, uint32_t c) {
    return r * 128u + ((c ^ (r & 7u)) << 4);
}

// ---------------------------------------------------------------------------
// Kernel 1: convert x1/x2 fp32 -> fp16 (vectorized, both in one launch)
// ---------------------------------------------------------------------------
__global__ void __launch_bounds__(256) convert_inputs_kernel(const float* __restrict__ x1,
                                                             const float* __restrict__ x2) {
    const int idx = blockIdx.x * blockDim.x + threadIdx.x;
    float4 v1 = __ldg((const float4*)x1 + idx);
    float4 v2 = __ldg((const float4*)x2 + idx);
    uint2 o1, o2;
    o1.x = f22h2(v1.x, v1.y); o1.y = f22h2(v1.z, v1.w);
    o2.x = f22h2(v2.x, v2.y); o2.y = f22h2(v2.z, v2.w);
    ((uint2*)g_x1h)[idx] = o1;
    ((uint2*)g_x2h)[idx] = o2;
}

// ---------------------------------------------------------------------------
// Kernel 2: W [k][p][q] fp32 -> Wt [k][q][p] fp16 (32x32 smem transpose)
// ---------------------------------------------------------------------------
__global__ void __launch_bounds__(256) transpose_w_kernel(const float* __restrict__ W) {
    __shared__ float tile[32][33];
    const int k  = blockIdx.z;
    const int p0 = blockIdx.x * 32;
    const int q0 = blockIdx.y * 32;
    const float* Wk = W + (size_t)k * ND1 * ND2;
#pragma unroll
    for (int yy = 0; yy < 32; yy += 8)
        tile[threadIdx.y + yy][threadIdx.x] =
            __ldg(&Wk[(size_t)(p0 + threadIdx.y + yy) * ND2 + q0 + threadIdx.x]);
    __syncthreads();
    __half* Wtk = g_wt + (size_t)k * ND2 * ND1;
#pragma unroll
    for (int yy = 0; yy < 32; yy += 8)
        Wtk[(size_t)(q0 + threadIdx.y + yy) * ND1 + p0 + threadIdx.x] =
            __float2half_rn(tile[threadIdx.x][threadIdx.y + yy]);
}

// ---------------------------------------------------------------------------
// GEMM1: tmp[bi][k][q] = sum_p x1h[bi][p] * Wt[k][q][p]   (TN, both K-major)
//   grid = (16 m-tiles of 128 bi, 4 q-tiles of 128, 64 k)
//   CTA 128x128, kc=64, 3-stage cp.async, 8 warps (2m x 4n), warp tile 64x32
// ---------------------------------------------------------------------------
#define G1_ASZ   (128u * 128u)           // 16384
#define G1_BSZ   (128u * 128u)           // 16384
#define G1_STAGE (G1_ASZ + G1_BSZ)       // 32768
#define G1_SMEM  (3u * G1_STAGE)         // 98304

__global__ void __launch_bounds__(256, 2) gemm1_kernel() {
    extern __shared__ char smem[];
    const int tid  = threadIdx.x;
    const int lane = tid & 31;
    const int wid  = tid >> 5;
    const int m0   = blockIdx.x * 128;
    const int q0   = blockIdx.y * 128;
    const int kb   = blockIdx.z;
    const uint32_t sb = smem_u32(smem);

    const __half* Ag = g_x1h + (size_t)m0 * ND1;
    const __half* Bg = g_wt + ((size_t)kb * ND2 + q0) * ND1;

    auto load_chunk = [&](int c, int stg) {
        uint32_t sA = sb + (uint32_t)stg * G1_STAGE;
        uint32_t sB = sA + G1_ASZ;
#pragma unroll
        for (int it = 0; it < 4; ++it) {
            int idx = tid + it * 256;
            uint32_t r = (uint32_t)(idx >> 3), col = (uint32_t)(idx & 7);
            cp16(sA + swz(r, col), Ag + (size_t)r * ND1 + c * 64 + col * 8);
        }
#pragma unroll
        for (int it = 0; it < 4; ++it) {
            int idx = tid + it * 256;
            uint32_t r = (uint32_t)(idx >> 3), col = (uint32_t)(idx & 7);
            cp16(sB + swz(r, col), Bg + (size_t)r * ND1 + c * 64 + col * 8);
        }
        cp_commit();
    };

    float d[4][4][4];
#pragma unroll
    for (int mf = 0; mf < 4; ++mf)
#pragma unroll
        for (int nf = 0; nf < 4; ++nf)
#pragma unroll
            for (int e = 0; e < 4; ++e) d[mf][nf][e] = 0.0f;

    const int m_base = (wid & 1) * 64;
    const int n_base = (wid >> 1) * 32;
    const uint32_t a_row = (uint32_t)(m_base + (lane & 15));
    const uint32_t a_cb  = (uint32_t)((lane >> 4) & 1);
    const uint32_t a_r7  = a_row & 7u;
    const uint32_t b_row = (uint32_t)(n_base + (lane & 7) + ((lane & 16) ? 8 : 0));
    const uint32_t b_cb  = (uint32_t)((lane >> 3) & 1);
    const uint32_t b_r7  = b_row & 7u;

    load_chunk(0, 0);
    load_chunk(1, 1);
#pragma unroll 1
    for (int c = 0; c < 8; ++c) {
        if (c < 7) cp_wait<1>(); else cp_wait<0>();
        __syncthreads();
        if (c + 2 < 8) load_chunk(c + 2, (c + 2) % 3);
        const uint32_t sA = sb + (uint32_t)(c % 3) * G1_STAGE;
        const uint32_t sB = sA + G1_ASZ;
#pragma unroll
        for (int s = 0; s < 4; ++s) {
            const uint32_t swA = ((2u * s + a_cb) ^ a_r7) << 4;
            const uint32_t swB = ((2u * s + b_cb) ^ b_r7) << 4;
            uint32_t a[4][4];
#pragma unroll
            for (int mf = 0; mf < 4; ++mf)
                ldm4(a[mf][0], a[mf][1], a[mf][2], a[mf][3],
                     sA + (a_row + mf * 16) * 128u + swA);
            uint32_t b[4][2];
#pragma unroll
            for (int nj = 0; nj < 2; ++nj) {
                uint32_t r0, r1, r2, r3;
                ldm4(r0, r1, r2, r3, sB + (b_row + nj * 16) * 128u + swB);
                b[2 * nj][0] = r0; b[2 * nj][1] = r1;
                b[2 * nj + 1][0] = r2; b[2 * nj + 1][1] = r3;
            }
#pragma unroll
            for (int mf = 0; mf < 4; ++mf)
#pragma unroll
                for (int nf = 0; nf < 4; ++nf)
                    mma16816(d[mf][nf], a[mf], b[nf]);
        }
    }

    // Epilogue: fp32 accum -> fp16 tmp[bi][k][q]
    {
        const int r_lane = lane >> 2;
        const int c_lane = (lane & 3) << 1;
#pragma unroll
        for (int mf = 0; mf < 4; ++mf) {
            const int row = m0 + m_base + mf * 16 + r_lane;
            __half* base = g_tmp + ((size_t)row * NK + kb) * ND2 + q0 + n_base + c_lane;
#pragma unroll
            for (int nf = 0; nf < 4; ++nf) {
                *(__half2*)(base + nf * 8) = __floats2half2_rn(d[mf][nf][0], d[mf][nf][1]);
                *(__half2*)(base + nf * 8 + (size_t)8 * NK * ND2) =
                    __floats2half2_rn(d[mf][nf][2], d[mf][nf][3]);
            }
        }
    }
}

// ---------------------------------------------------------------------------
// GEMM2: out[bi][j][k] = sum_q x2h[b][j][q] * tmp[bi][k][q] + bias[k]
//   Restructured: CTA handles a bi-PAIR. Since g_tmp rows for consecutive bi
//   are contiguous, the B operand is one contiguous 128x512 fp16 block
//   (rows 0-63 = bi0 k's, rows 64-127 = bi1 k's). Output tile 128(j) x 128(n),
//   n = bi_sel*64 + k. Same config as gemm1: 256 thr, 8 warps (2m x 4n),
//   warp 64x32, 3-stage, 96KB smem -> 2 CTAs/SM, 16 warps/SM.
//   grid = (2 j-tiles, 1024 bi-pairs)
// ---------------------------------------------------------------------------
#define G2_ASZ   (128u * 128u)           // 16384
#define G2_BSZ   (128u * 128u)           // 16384
#define G2_STAGE (G2_ASZ + G2_BSZ)       // 32768
#define G2_SMEM  (3u * G2_STAGE)         // 98304

__global__ void __launch_bounds__(256, 2) gemm2_kernel(const float* __restrict__ bias,
                                                       float* __restrict__ out) {
    __shared__ float sbias[64];
    extern __shared__ char smem[];
    const int tid  = threadIdx.x;
    const int lane = tid & 31;
    const int wid  = tid >> 5;
    const int j0   = blockIdx.x * 128;
    const int bi0  = blockIdx.y * 2;
    const int b    = bi0 >> 8;
    const uint32_t sb = smem_u32(smem);

    if (tid < 64) sbias[tid] = __ldg(bias + tid);

    const __half* Ag = g_x2h + ((size_t)(b * NL) + j0) * ND2;
    const __half* Bg = g_tmp + (size_t)bi0 * NK * ND2;   // contiguous 128x512

    auto load_chunk = [&](int c, int stg) {
        uint32_t sA = sb + (uint32_t)stg * G2_STAGE;
        uint32_t sB = sA + G2_ASZ;
#pragma unroll
        for (int it = 0; it < 4; ++it) {
            int idx = tid + it * 256;
            uint32_t r = (uint32_t)(idx >> 3), col = (uint32_t)(idx & 7);
            cp16(sA + swz(r, col), Ag + (size_t)r * ND2 + c * 64 + col * 8);
        }
#pragma unroll
        for (int it = 0; it < 4; ++it) {
            int idx = tid + it * 256;
            uint32_t r = (uint32_t)(idx >> 3), col = (uint32_t)(idx & 7);
            cp16(sB + swz(r, col), Bg + (size_t)r * ND2 + c * 64 + col * 8);
        }
        cp_commit();
    };

    float d[4][4][4];
#pragma unroll
    for (int mf = 0; mf < 4; ++mf)
#pragma unroll
        for (int nf = 0; nf < 4; ++nf)
#pragma unroll
            for (int e = 0; e < 4; ++e) d[mf][nf][e] = 0.0f;

    const int m_base = (wid & 1) * 64;
    const int n_base = (wid >> 1) * 32;
    const uint32_t a_row = (uint32_t)(m_base + (lane & 15));
    const uint32_t a_cb  = (uint32_t)((lane >> 4) & 1);
    const uint32_t a_r7  = a_row & 7u;
    const uint32_t b_row = (uint32_t)(n_base + (lane & 7) + ((lane & 16) ? 8 : 0));
    const uint32_t b_cb  = (uint32_t)((lane >> 3) & 1);
    const uint32_t b_r7  = b_row & 7u;

    load_chunk(0, 0);
    load_chunk(1, 1);
#pragma unroll 1
    for (int c = 0; c < 8; ++c) {
        if (c < 7) cp_wait<1>(); else cp_wait<0>();
        __syncthreads();
        if (c + 2 < 8) load_chunk(c + 2, (c + 2) % 3);
        const uint32_t sA = sb + (uint32_t)(c % 3) * G2_STAGE;
        const uint32_t sB = sA + G2_ASZ;
#pragma unroll
        for (int s = 0; s < 4; ++s) {
            const uint32_t swA = ((2u * s + a_cb) ^ a_r7) << 4;
            const uint32_t swB = ((2u * s + b_cb) ^ b_r7) << 4;
            uint32_t a[4][4];
#pragma unroll
            for (int mf = 0; mf < 4; ++mf)
                ldm4(a[mf][0], a[mf][1], a[mf][2], a[mf][3],
                     sA + (a_row + mf * 16) * 128u + swA);
            uint32_t bfr[4][2];
#pragma unroll
            for (int nj = 0; nj < 2; ++nj) {
                uint32_t r0, r1, r2, r3;
                ldm4(r0, r1, r2, r3, sB + (b_row + nj * 16) * 128u + swB);
                bfr[2 * nj][0] = r0; bfr[2 * nj][1] = r1;
                bfr[2 * nj + 1][0] = r2; bfr[2 * nj + 1][1] = r3;
            }
#pragma unroll
            for (int mf = 0; mf < 4; ++mf)
#pragma unroll
                for (int nf = 0; nf < 4; ++nf)
                    mma16816(d[mf][nf], a[mf], bfr[nf]);
        }
    }

    // Epilogue: + bias -> out[bi][j][k]. Warp-uniform bi select: n_base>=64 -> bi1.
    {
        const int r_lane = lane >> 2;
        const int c_lane = (lane & 3) << 1;
        const int bi     = bi0 + (n_base >> 6);
        const int k_base = n_base & 63;
#pragma unroll
        for (int mf = 0; mf < 4; ++mf) {
            const int jrow = j0 + m_base + mf * 16 + r_lane;
            float* base = out + ((size_t)bi * NL + jrow) * NK;
#pragma unroll
            for (int nf = 0; nf < 4; ++nf) {
                const int kc0 = k_base + nf * 8 + c_lane;
                const float b0 = sbias[kc0], b1 = sbias[kc0 + 1];
                *(float2*)(base + kc0) = make_float2(d[mf][nf][0] + b0, d[mf][nf][1] + b1);
                *(float2*)(base + 8 * NK + kc0) =
                    make_float2(d[mf][nf][2] + b0, d[mf][nf][3] + b1);
            }
        }
    }
}

// ---------------------------------------------------------------------------
// Launch
// ---------------------------------------------------------------------------
extern "C" void kernel_launch(void* const* d_in, const int* in_sizes, int n_in,
                              void* d_out, int out_size) {
    const float* x1   = (const float*)d_in[0];
    const float* x2   = (const float*)d_in[1];
    const float* W    = (const float*)d_in[2];
    const float* bias = (const float*)d_in[3];
    float* out = (float*)d_out;

    cudaFuncSetAttribute(gemm1_kernel, cudaFuncAttributeMaxDynamicSharedMemorySize, G1_SMEM);
    cudaFuncSetAttribute(gemm2_kernel, cudaFuncAttributeMaxDynamicSharedMemorySize, G2_SMEM);

    convert_inputs_kernel<<<1024, 256>>>(x1, x2);
    transpose_w_kernel<<<dim3(16, 16, 64), dim3(32, 8)>>>(W);
    gemm1_kernel<<<dim3(16, 4, 64), 256, G1_SMEM>>>();
    gemm2_kernel<<<dim3(2, 1024), 256, G2_SMEM>>>(bias, out);
}

// round 12
// speedup vs baseline: 1.8731x; 1.0144x over previous
#include <cuda_runtime.h>
#include <cuda_fp16.h>
#include <cstdint>

// Problem dims (fixed by the reference)
#define NB   8
#define NL   256
#define ND1  512
#define ND2  512
#define NK   64
#define NBI  (NB * NL)   // 2048

// ---------------------------------------------------------------------------
// Scratch (static __device__ arrays: allocation-guard-safe)
// ---------------------------------------------------------------------------
__device__ __half g_x1h[NBI * ND1];                       // x1 fp16              (2 MB)
__device__ __half g_x2h[NBI * ND2];                       // x2 fp16              (2 MB)
__device__ __half g_wt [(size_t)NK * ND2 * ND1];          // W^T [k][q][p] fp16   (32 MB)
__device__ __half g_tmp[(size_t)NBI * NK * ND2];          // tmp [bi][k][q] fp16  (128 MB)

// ---------------------------------------------------------------------------
// Portable (sm_80-level) PTX helpers — NO 'a'-gated features anywhere
// ---------------------------------------------------------------------------
__device__ __forceinline__ uint32_t smem_u32(const void* p) {
    uint32_t a;
    asm("{ .reg .u64 t; cvta.to.shared.u64 t, %1; cvt.u32.u64 %0, t; }" : "=r"(a) : "l"(p));
    return a;
}

__device__ __forceinline__ void cp16(uint32_t saddr, const void* gaddr) {
    asm volatile("cp.async.cg.shared.global [%0], [%1], 16;" :: "r"(saddr), "l"(gaddr));
}
__device__ __forceinline__ void cp_commit() {
    asm volatile("cp.async.commit_group;" ::: "memory");
}
template <int N>
__device__ __forceinline__ void cp_wait() {
    asm volatile("cp.async.wait_group %0;" :: "n"(N) : "memory");
}

__device__ __forceinline__ void ldm4(uint32_t& r0, uint32_t& r1, uint32_t& r2, uint32_t& r3,
                                     uint32_t addr) {
    asm volatile("ldmatrix.sync.aligned.m8n8.x4.shared.b16 {%0,%1,%2,%3}, [%4];"
                 : "=r"(r0), "=r"(r1), "=r"(r2), "=r"(r3) : "r"(addr));
}

__device__ __forceinline__ void mma16816(float* d, const uint32_t* a, const uint32_t* b) {
    asm volatile(
        "mma.sync.aligned.m16n8k16.row.col.f32.f16.f16.f32 "
        "{%0,%1,%2,%3}, {%4,%5,%6,%7}, {%8,%9}, {%0,%1,%2,%3};"
        : "+f"(d[0]), "+f"(d[1]), "+f"(d[2]), "+f"(d[3])
        : "r"(a[0]), "r"(a[1]), "r"(a[2]), "r"(a[3]), "r"(b[0]), "r"(b[1]));
}

__device__ __forceinline__ uint32_t f22h2(float lo, float hi) {
    uint32_t r;
    asm("cvt.rn.f16x2.f32 %0, %1, %2;" : "=r"(r) : "f"(hi), "f"(lo));
    return r;
}

// XOR swizzle: tile rows are 128B (8 x 16B chunks); chunk column c of row r
// lives at (c ^ (r & 7)) * 16. Conflict-free for cp.async stores and
// ldmatrix reads; no row padding needed.
__device__ __forceinline__ uint32_t swz(uint32_t r, uint32_t c) {
    return r * 128u + ((c ^ (r & 7u)) << 4);
}

// ---------------------------------------------------------------------------
// Kernel 1: convert x1/x2 fp32 -> fp16 (vectorized, both in one launch)
// ---------------------------------------------------------------------------
__global__ void __launch_bounds__(256) convert_inputs_kernel(const float* __restrict__ x1,
                                                             const float* __restrict__ x2) {
    const int idx = blockIdx.x * blockDim.x + threadIdx.x;
    float4 v1 = __ldg((const float4*)x1 + idx);
    float4 v2 = __ldg((const float4*)x2 + idx);
    uint2 o1, o2;
    o1.x = f22h2(v1.x, v1.y); o1.y = f22h2(v1.z, v1.w);
    o2.x = f22h2(v2.x, v2.y); o2.y = f22h2(v2.z, v2.w);
    ((uint2*)g_x1h)[idx] = o1;
    ((uint2*)g_x2h)[idx] = o2;
}

// ---------------------------------------------------------------------------
// Kernel 2: W [k][p][q] fp32 -> Wt [k][q][p] fp16
//   64(p) x 32(q) tiles; fp32 coalesced loads, __half2 coalesced stores.
// ---------------------------------------------------------------------------
__global__ void __launch_bounds__(256) transpose_w_kernel(const float* __restrict__ W) {
    __shared__ float tile[64][33];
    const int tid = threadIdx.x;
    const int k  = blockIdx.z;
    const int p0 = blockIdx.x * 64;
    const int q0 = blockIdx.y * 32;
    const float* Wk = W + (size_t)k * ND1 * ND2;
    const int tx = tid & 31, ty = tid >> 5;   // 32 q-cols, 8 p-rows per pass
#pragma unroll
    for (int yy = 0; yy < 64; yy += 8)
        tile[ty + yy][tx] = __ldg(&Wk[(size_t)(p0 + ty + yy) * ND2 + q0 + tx]);
    __syncthreads();
    __half* Wtk = g_wt + (size_t)k * ND2 * ND1;
    const int pc = tid & 31;                  // half2 index along p (0..31)
    const int qr = tid >> 5;                  // q-row per pass
#pragma unroll
    for (int qq = 0; qq < 32; qq += 8) {
        const int q = qq + qr;
        __half2 h = __floats2half2_rn(tile[2 * pc][q], tile[2 * pc + 1][q]);
        *(__half2*)(&Wtk[(size_t)(q0 + q) * ND1 + p0 + 2 * pc]) = h;
    }
}

// ---------------------------------------------------------------------------
// GEMM1: tmp[bi][k][q] = sum_p x1h[bi][p] * Wt[k][q][p]   (TN, both K-major)
//   grid = (16 m-tiles of 128 bi, 4 q-tiles of 128, 64 k)
//   CTA 128x128, kc=64, 3-stage cp.async, 8 warps (2m x 4n), warp tile 64x32.
//   cp.async for stage c+2 is interleaved into the 4 s-steps (2 cp16/s) to
//   avoid the post-barrier LSU burst that idles the tensor pipe.
// ---------------------------------------------------------------------------
#define G1_ASZ   (128u * 128u)           // 16384
#define G1_BSZ   (128u * 128u)           // 16384
#define G1_STAGE (G1_ASZ + G1_BSZ)       // 32768
#define G1_SMEM  (3u * G1_STAGE)         // 98304

__global__ void __launch_bounds__(256, 2) gemm1_kernel() {
    extern __shared__ char smem[];
    const int tid  = threadIdx.x;
    const int lane = tid & 31;
    const int wid  = tid >> 5;
    const int m0   = blockIdx.x * 128;
    const int q0   = blockIdx.y * 128;
    const int kb   = blockIdx.z;
    const uint32_t sb = smem_u32(smem);

    const __half* Ag = g_x1h + (size_t)m0 * ND1;
    const __half* Bg = g_wt + ((size_t)kb * ND2 + q0) * ND1;

    // per-thread load coords (same for all chunks)
    const uint32_t ld_r = (uint32_t)(tid >> 3);         // row within 1/4 tile slice? no:
    // full-tile coords per s-slice: idx = tid + s*256 -> r = idx>>3, col = idx&7
    auto load_full = [&](int c, int stg) {
        uint32_t sA = sb + (uint32_t)stg * G1_STAGE;
        uint32_t sB = sA + G1_ASZ;
#pragma unroll
        for (int it = 0; it < 4; ++it) {
            int idx = tid + it * 256;
            uint32_t r = (uint32_t)(idx >> 3), col = (uint32_t)(idx & 7);
            cp16(sA + swz(r, col), Ag + (size_t)r * ND1 + c * 64 + col * 8);
            cp16(sB + swz(r, col), Bg + (size_t)r * ND1 + c * 64 + col * 8);
        }
        cp_commit();
    };
    (void)ld_r;

    float d[4][4][4];
#pragma unroll
    for (int mf = 0; mf < 4; ++mf)
#pragma unroll
        for (int nf = 0; nf < 4; ++nf)
#pragma unroll
            for (int e = 0; e < 4; ++e) d[mf][nf][e] = 0.0f;

    const int m_base = (wid & 1) * 64;
    const int n_base = (wid >> 1) * 32;
    const uint32_t a_row = (uint32_t)(m_base + (lane & 15));
    const uint32_t a_cb  = (uint32_t)((lane >> 4) & 1);
    const uint32_t a_r7  = a_row & 7u;
    const uint32_t b_row = (uint32_t)(n_base + (lane & 7) + ((lane & 16) ? 8 : 0));
    const uint32_t b_cb  = (uint32_t)((lane >> 3) & 1);
    const uint32_t b_r7  = b_row & 7u;

    load_full(0, 0);
    load_full(1, 1);
#pragma unroll 1
    for (int c = 0; c < 8; ++c) {
        if (c < 7) cp_wait<1>(); else cp_wait<0>();
        __syncthreads();
        const bool pf = (c + 2 < 8);
        const uint32_t pstg = (uint32_t)((c + 2) % 3);
        const uint32_t pA = sb + pstg * G1_STAGE;
        const uint32_t pB = pA + G1_ASZ;
        const __half* gAp = Ag + (c + 2) * 64;
        const __half* gBp = Bg + (c + 2) * 64;
        const uint32_t sA = sb + (uint32_t)(c % 3) * G1_STAGE;
        const uint32_t sB = sA + G1_ASZ;
#pragma unroll
        for (int s = 0; s < 4; ++s) {
            // interleaved prefetch of stage c+2 (slice s): 1 A + 1 B cp16
            if (pf) {
                int idx = tid + s * 256;
                uint32_t r = (uint32_t)(idx >> 3), col = (uint32_t)(idx & 7);
                cp16(pA + swz(r, col), gAp + (size_t)r * ND1 + col * 8);
                cp16(pB + swz(r, col), gBp + (size_t)r * ND1 + col * 8);
            }
            const uint32_t swA = ((2u * s + a_cb) ^ a_r7) << 4;
            const uint32_t swB = ((2u * s + b_cb) ^ b_r7) << 4;
            uint32_t a[4][4];
#pragma unroll
            for (int mf = 0; mf < 4; ++mf)
                ldm4(a[mf][0], a[mf][1], a[mf][2], a[mf][3],
                     sA + (a_row + mf * 16) * 128u + swA);
            uint32_t b[4][2];
#pragma unroll
            for (int nj = 0; nj < 2; ++nj) {
                uint32_t r0, r1, r2, r3;
                ldm4(r0, r1, r2, r3, sB + (b_row + nj * 16) * 128u + swB);
                b[2 * nj][0] = r0; b[2 * nj][1] = r1;
                b[2 * nj + 1][0] = r2; b[2 * nj + 1][1] = r3;
            }
#pragma unroll
            for (int mf = 0; mf < 4; ++mf)
#pragma unroll
                for (int nf = 0; nf < 4; ++nf)
                    mma16816(d[mf][nf], a[mf], b[nf]);
        }
        if (pf) cp_commit();
    }

    // Epilogue: fp32 accum -> fp16 tmp[bi][k][q]
    {
        const int r_lane = lane >> 2;
        const int c_lane = (lane & 3) << 1;
#pragma unroll
        for (int mf = 0; mf < 4; ++mf) {
            const int row = m0 + m_base + mf * 16 + r_lane;
            __half* base = g_tmp + ((size_t)row * NK + kb) * ND2 + q0 + n_base + c_lane;
#pragma unroll
            for (int nf = 0; nf < 4; ++nf) {
                *(__half2*)(base + nf * 8) = __floats2half2_rn(d[mf][nf][0], d[mf][nf][1]);
                *(__half2*)(base + nf * 8 + (size_t)8 * NK * ND2) =
                    __floats2half2_rn(d[mf][nf][2], d[mf][nf][3]);
            }
        }
    }
}

// ---------------------------------------------------------------------------
// GEMM2: out[bi][j][k] = sum_q x2h[b][j][q] * tmp[bi][k][q] + bias[k]
//   CTA handles a bi-PAIR (B operand = contiguous 128x512 fp16 block).
//   Output tile 128(j) x 128(n), n = bi_sel*64 + k. 256 thr, 8 warps (2m x 4n),
//   warp 64x32, 3-stage, interleaved cp.async. grid = (2 j-tiles, 1024 pairs).
// ---------------------------------------------------------------------------
#define G2_ASZ   (128u * 128u)           // 16384
#define G2_BSZ   (128u * 128u)           // 16384
#define G2_STAGE (G2_ASZ + G2_BSZ)       // 32768
#define G2_SMEM  (3u * G2_STAGE)         // 98304

__global__ void __launch_bounds__(256, 2) gemm2_kernel(const float* __restrict__ bias,
                                                       float* __restrict__ out) {
    __shared__ float sbias[64];
    extern __shared__ char smem[];
    const int tid  = threadIdx.x;
    const int lane = tid & 31;
    const int wid  = tid >> 5;
    const int j0   = blockIdx.x * 128;
    const int bi0  = blockIdx.y * 2;
    const int b    = bi0 >> 8;
    const uint32_t sb = smem_u32(smem);

    if (tid < 64) sbias[tid] = __ldg(bias + tid);

    const __half* Ag = g_x2h + ((size_t)(b * NL) + j0) * ND2;
    const __half* Bg = g_tmp + (size_t)bi0 * NK * ND2;   // contiguous 128x512

    auto load_full = [&](int c, int stg) {
        uint32_t sA = sb + (uint32_t)stg * G2_STAGE;
        uint32_t sB = sA + G2_ASZ;
#pragma unroll
        for (int it = 0; it < 4; ++it) {
            int idx = tid + it * 256;
            uint32_t r = (uint32_t)(idx >> 3), col = (uint32_t)(idx & 7);
            cp16(sA + swz(r, col), Ag + (size_t)r * ND2 + c * 64 + col * 8);
            cp16(sB + swz(r, col), Bg + (size_t)r * ND2 + c * 64 + col * 8);
        }
        cp_commit();
    };

    float d[4][4][4];
#pragma unroll
    for (int mf = 0; mf < 4; ++mf)
#pragma unroll
        for (int nf = 0; nf < 4; ++nf)
#pragma unroll
            for (int e = 0; e < 4; ++e) d[mf][nf][e] = 0.0f;

    const int m_base = (wid & 1) * 64;
    const int n_base = (wid >> 1) * 32;
    const uint32_t a_row = (uint32_t)(m_base + (lane & 15));
    const uint32_t a_cb  = (uint32_t)((lane >> 4) & 1);
    const uint32_t a_r7  = a_row & 7u;
    const uint32_t b_row = (uint32_t)(n_base + (lane & 7) + ((lane & 16) ? 8 : 0));
    const uint32_t b_cb  = (uint32_t)((lane >> 3) & 1);
    const uint32_t b_r7  = b_row & 7u;

    load_full(0, 0);
    load_full(1, 1);
#pragma unroll 1
    for (int c = 0; c < 8; ++c) {
        if (c < 7) cp_wait<1>(); else cp_wait<0>();
        __syncthreads();
        const bool pf = (c + 2 < 8);
        const uint32_t pstg = (uint32_t)((c + 2) % 3);
        const uint32_t pA = sb + pstg * G2_STAGE;
        const uint32_t pB = pA + G2_ASZ;
        const __half* gAp = Ag + (c + 2) * 64;
        const __half* gBp = Bg + (c + 2) * 64;
        const uint32_t sA = sb + (uint32_t)(c % 3) * G2_STAGE;
        const uint32_t sB = sA + G2_ASZ;
#pragma unroll
        for (int s = 0; s < 4; ++s) {
            if (pf) {
                int idx = tid + s * 256;
                uint32_t r = (uint32_t)(idx >> 3), col = (uint32_t)(idx & 7);
                cp16(pA + swz(r, col), gAp + (size_t)r * ND2 + col * 8);
                cp16(pB + swz(r, col), gBp + (size_t)r * ND2 + col * 8);
            }
            const uint32_t swA = ((2u * s + a_cb) ^ a_r7) << 4;
            const uint32_t swB = ((2u * s + b_cb) ^ b_r7) << 4;
            uint32_t a[4][4];
#pragma unroll
            for (int mf = 0; mf < 4; ++mf)
                ldm4(a[mf][0], a[mf][1], a[mf][2], a[mf][3],
                     sA + (a_row + mf * 16) * 128u + swA);
            uint32_t bfr[4][2];
#pragma unroll
            for (int nj = 0; nj < 2; ++nj) {
                uint32_t r0, r1, r2, r3;
                ldm4(r0, r1, r2, r3, sB + (b_row + nj * 16) * 128u + swB);
                bfr[2 * nj][0] = r0; bfr[2 * nj][1] = r1;
                bfr[2 * nj + 1][0] = r2; bfr[2 * nj + 1][1] = r3;
            }
#pragma unroll
            for (int mf = 0; mf < 4; ++mf)
#pragma unroll
                for (int nf = 0; nf < 4; ++nf)
                    mma16816(d[mf][nf], a[mf], bfr[nf]);
        }
        if (pf) cp_commit();
    }

    // Epilogue: + bias -> out[bi][j][k]. Warp-uniform bi select: n_base>=64 -> bi1.
    {
        const int r_lane = lane >> 2;
        const int c_lane = (lane & 3) << 1;
        const int bi     = bi0 + (n_base >> 6);
        const int k_base = n_base & 63;
#pragma unroll
        for (int mf = 0; mf < 4; ++mf) {
            const int jrow = j0 + m_base + mf * 16 + r_lane;
            float* base = out + ((size_t)bi * NL + jrow) * NK;
#pragma unroll
            for (int nf = 0; nf < 4; ++nf) {
                const int kc0 = k_base + nf * 8 + c_lane;
                const float b0 = sbias[kc0], b1 = sbias[kc0 + 1];
                *(float2*)(base + kc0) = make_float2(d[mf][nf][0] + b0, d[mf][nf][1] + b1);
                *(float2*)(base + 8 * NK + kc0) =
                    make_float2(d[mf][nf][2] + b0, d[mf][nf][3] + b1);
            }
        }
    }
}

// ---------------------------------------------------------------------------
// Launch
// ---------------------------------------------------------------------------
extern "C" void kernel_launch(void* const* d_in, const int* in_sizes, int n_in,
                              void* d_out, int out_size) {
    const float* x1   = (const float*)d_in[0];
    const float* x2   = (const float*)d_in[1];
    const float* W    = (const float*)d_in[2];
    const float* bias = (const float*)d_in[3];
    float* out = (float*)d_out;

    cudaFuncSetAttribute(gemm1_kernel, cudaFuncAttributeMaxDynamicSharedMemorySize, G1_SMEM);
    cudaFuncSetAttribute(gemm2_kernel, cudaFuncAttributeMaxDynamicSharedMemorySize, G2_SMEM);

    convert_inputs_kernel<<<1024, 256>>>(x1, x2);
    transpose_w_kernel<<<dim3(8, 16, 64), 256>>>(W);
    gemm1_kernel<<<dim3(16, 4, 64), 256, G1_SMEM>>>();
    gemm2_kernel<<<dim3(2, 1024), 256, G2_SMEM>>>(bias, out);
}